// round 11
// baseline (speedup 1.0000x reference)
#include <cuda_runtime.h>

#define WIN   48
#define HALO  47
#define BK    192             // 6 warps = 12 half-warp segments
#define WPB   480             // outputs per block (10 x 48)
#define NBB   11              // beta 48-blocks: betas i in [0, 528)
#define NMB   12              // moment 48-blocks: rows [0, 576)
#define TXR   576             // row span per block
#define XOFF  0.75f

// ---- shared layout (no x staging buffer: x is read directly from gmem; the
// output pass re-reads hit L1) ----
// [ s_p0 float4*NMB*49 | s_p1 float4*NMB*49 | s_p2 float*NMB*49 ]
//   s_bp (float4*NBB*49) aliases s_p0 after barrier B3.
#define SMEM_TOT ((2 * NMB * 49 * 16 + NMB * 49 * 4 + 15) & ~15)

__device__ __forceinline__ float rcp_fast(float a) {
    float r; asm("rcp.approx.f32 %0, %1;" : "=f"(r) : "f"(a)); return r;
}
__device__ __forceinline__ float rsqrt_fast(float a) {
    float r; asm("rsqrt.approx.f32 %0, %1;" : "=f"(r) : "f"(a)); return r;
}

__global__ __launch_bounds__(BK, 7)
void pos_kernel(const float* __restrict__ x, const float* __restrict__ Wm,
                float* __restrict__ H, int N, int K) {
    __shared__ __align__(16) char smem[SMEM_TOT];
    float4* s_p0 = (float4*)smem;                      // {Sx,Sy,Sz,Mxx} prefixes
    float4* s_p1 = s_p0 + NMB * 49;                    // {Myy,Mzz,Mxy,Mxz}
    float*  s_p2 = (float*)(s_p1 + NMB * 49);          // Myz
    float4* s_bp = (float4*)smem;                      // beta prefixes (alias s_p0)

    const int t  = threadIdx.x;
    const int sl = t & 15;              // lane in half-warp segment
    const int hw = t >> 4;              // half-warp id 0..11
    const int n0 = blockIdx.x * WPB;
    const int kb = n0 - HALO;           // global row of local index 0

    const float W00 = Wm[0], W01 = Wm[1], W02 = Wm[2];
    const float W10 = Wm[3], W11 = Wm[4], W12 = Wm[5];
    const float r0 = W00 + W01 + W02;
    const float r1 = W10 + W11 + W12;

    // interior: every row [kb, kb+TXR) is in range -> unpredicated loads
    const bool interior = (kb >= 0) && (kb + TXR <= N);

    // ================= moment pass: local 48-block prefixes =================
    {
        const int grow = kb + 48 * hw + 3 * sl;    // first of this lane's 3 rows
        float X0, Y0, Z0, X1, Y1, Z1, X2, Y2, Z2;
        if (interior) {
            const float* gp = x + 3 * grow;
            X0 = gp[0] - XOFF; Y0 = gp[1] - XOFF; Z0 = gp[2] - XOFF;
            X1 = gp[3] - XOFF; Y1 = gp[4] - XOFF; Z1 = gp[5] - XOFF;
            X2 = gp[6] - XOFF; Y2 = gp[7] - XOFF; Z2 = gp[8] - XOFF;
        } else {
            const bool v0 = (grow >= 0)     && (grow < N);
            const bool v1 = (grow + 1 >= 0) && (grow + 1 < N);
            const bool v2 = (grow + 2 >= 0) && (grow + 2 < N);
            const float* gp = x + 3 * grow;
            X0 = v0 ? gp[0] - XOFF : 0.f; Y0 = v0 ? gp[1] - XOFF : 0.f; Z0 = v0 ? gp[2] - XOFF : 0.f;
            X1 = v1 ? gp[3] - XOFF : 0.f; Y1 = v1 ? gp[4] - XOFF : 0.f; Z1 = v1 ? gp[5] - XOFF : 0.f;
            X2 = v2 ? gp[6] - XOFF : 0.f; Y2 = v2 ? gp[7] - XOFF : 0.f; Z2 = v2 ? gp[8] - XOFF : 0.f;
        }

        float v[9];
        v[0] = X0 + X1 + X2; v[1] = Y0 + Y1 + Y2; v[2] = Z0 + Z1 + Z2;
        v[3] = fmaf(X2, X2, fmaf(X1, X1, X0 * X0));
        v[4] = fmaf(Y2, Y2, fmaf(Y1, Y1, Y0 * Y0));
        v[5] = fmaf(Z2, Z2, fmaf(Z1, Z1, Z0 * Z0));
        v[6] = fmaf(X2, Y2, fmaf(X1, Y1, X0 * Y0));
        v[7] = fmaf(X2, Z2, fmaf(X1, Z1, X0 * Z0));
        v[8] = fmaf(Y2, Z2, fmaf(Y1, Z1, Y0 * Z0));

        float p[9];
#pragma unroll
        for (int c = 0; c < 9; ++c) p[c] = v[c];
#pragma unroll
        for (int d = 1; d < 16; d <<= 1) {
#pragma unroll
            for (int c = 0; c < 9; ++c) {
                const float u = __shfl_up_sync(0xffffffffu, p[c], d);
                if (sl >= d) p[c] += u;
            }
        }

        float e[9];
#pragma unroll
        for (int c = 0; c < 9; ++c) e[c] = p[c] - v[c];   // exclusive at chunk start
        const int bp = 49 * hw + 3 * sl;
        s_p0[bp] = make_float4(e[0], e[1], e[2], e[3]);
        s_p1[bp] = make_float4(e[4], e[5], e[6], e[7]);
        s_p2[bp] = e[8];
        e[0] += X0; e[1] += Y0; e[2] += Z0;
        e[3] = fmaf(X0, X0, e[3]); e[4] = fmaf(Y0, Y0, e[4]); e[5] = fmaf(Z0, Z0, e[5]);
        e[6] = fmaf(X0, Y0, e[6]); e[7] = fmaf(X0, Z0, e[7]); e[8] = fmaf(Y0, Z0, e[8]);
        s_p0[bp + 1] = make_float4(e[0], e[1], e[2], e[3]);
        s_p1[bp + 1] = make_float4(e[4], e[5], e[6], e[7]);
        s_p2[bp + 1] = e[8];
        e[0] += X1; e[1] += Y1; e[2] += Z1;
        e[3] = fmaf(X1, X1, e[3]); e[4] = fmaf(Y1, Y1, e[4]); e[5] = fmaf(Z1, Z1, e[5]);
        e[6] = fmaf(X1, Y1, e[6]); e[7] = fmaf(X1, Z1, e[7]); e[8] = fmaf(Y1, Z1, e[8]);
        s_p0[bp + 2] = make_float4(e[0], e[1], e[2], e[3]);
        s_p1[bp + 2] = make_float4(e[4], e[5], e[6], e[7]);
        s_p2[bp + 2] = e[8];
        if (sl == 15) {   // block total at position 48
            e[0] += X2; e[1] += Y2; e[2] += Z2;
            e[3] = fmaf(X2, X2, e[3]); e[4] = fmaf(Y2, Y2, e[4]); e[5] = fmaf(Z2, Z2, e[5]);
            e[6] = fmaf(X2, Y2, e[6]); e[7] = fmaf(X2, Z2, e[7]); e[8] = fmaf(Y2, Z2, e[8]);
            const int bt = 49 * hw + 48;
            s_p0[bt] = make_float4(e[0], e[1], e[2], e[3]);
            s_p1[bt] = make_float4(e[4], e[5], e[6], e[7]);
            s_p2[bt] = e[8];
        }
    }
    __syncthreads();                                             // B2

    // ========== beta pass: 3 betas/lane, held in regs + segmented scan ==========
    float4 vb[3];
    float e0, e1, e2, e3;
    {
        const int blkL = (hw < NBB) ? hw : (NBB - 1);   // clamp for loads only
        const int o0 = 3 * sl;
        const int lo = (kb < 0) ? -kb : 0;
        const int hi = (K - kb < NBB * 48) ? (K - kb) : (NBB * 48);

        const float4 T0 = s_p0[49 * blkL + 48];
        const float4 T1 = s_p1[49 * blkL + 48];
        const float  Tz = s_p2[49 * blkL + 48];

        float v4[4] = {0.f, 0.f, 0.f, 0.f};
#pragma unroll
        for (int r = 0; r < 3; ++r) {
            const int o = o0 + r;
            const float4 A0 = s_p0[49 * blkL + o];
            const float4 A1 = s_p1[49 * blkL + o];
            const float  Az = s_p2[49 * blkL + o];
            const float4 B0 = s_p0[49 * (blkL + 1) + o];
            const float4 B1 = s_p1[49 * (blkL + 1) + o];
            const float  Bz = s_p2[49 * (blkL + 1) + o];

            float4 out = make_float4(0.f, 0.f, 0.f, 0.f);
            const int i = 48 * hw + o;
            if (i >= lo && i < hi) {
                const float Sx  = T0.x - A0.x + B0.x;
                const float Sy  = T0.y - A0.y + B0.y;
                const float Sz  = T0.z - A0.z + B0.z;
                const float Mxx = T0.w - A0.w + B0.w;
                const float Myy = T1.x - A1.x + B1.x;
                const float Mzz = T1.y - A1.y + B1.y;
                const float Mxy = T1.z - A1.z + B1.z;
                const float Mxz = T1.w - A1.w + B1.w;
                const float Myz = Tz   - Az   + Bz;

                // batch inversion: one rcp serves all three channel means
                const float Sxp = Sx + 48.f * XOFF;   // = 48*m_r
                const float Syp = Sy + 48.f * XOFF;
                const float Szp = Sz + 48.f * XOFF;
                const float Pyz = Syp * Szp, Pxz = Sxp * Szp, Pxy = Sxp * Syp;
                const float inv = rcp_fast(Pyz * Sxp);   // 1/(Sxp*Syp*Szp)

                // alpha is scale-invariant: use UNSCALED coefficients
                const float a0r = W00 * Pyz, a0g = W01 * Pxz, a0b = W02 * Pxy;
                const float a1r = W10 * Pyz, a1g = W11 * Pxz, a1b = W12 * Pxy;
                const float T0s = a0r * Sx + a0g * Sy + a0b * Sz;
                const float T1s = a1r * Sx + a1g * Sy + a1b * Sz;
                const float q0 = a0r * a0r * Mxx + a0g * a0g * Myy + a0b * a0b * Mzz
                               + 2.f * (a0r * a0g * Mxy + a0r * a0b * Mxz + a0g * a0b * Myz)
                               - T0s * T0s * (1.f / 48.f);
                const float q1 = a1r * a1r * Mxx + a1g * a1g * Myy + a1b * a1b * Mzz
                               + 2.f * (a1r * a1g * Mxy + a1r * a1b * Mxz + a1g * a1b * Myz)
                               - T1s * T1s * (1.f / 48.f);
                const float alpha = q0 * rsqrt_fast(q0 * q1);   // sqrt(q0/q1)

                const float c48inv = 48.f * inv;
                out.x = fmaf(alpha, W10, W00) * (Pyz * c48inv);
                out.y = fmaf(alpha, W11, W01) * (Pxz * c48inv);
                out.z = fmaf(alpha, W12, W02) * (Pxy * c48inv);
                out.w = fmaf(alpha, r1, r0);                    // beta . m (exact)
            }
            vb[r] = out;
            v4[0] += out.x; v4[1] += out.y; v4[2] += out.z; v4[3] += out.w;
        }

        float p4[4];
#pragma unroll
        for (int c = 0; c < 4; ++c) p4[c] = v4[c];
#pragma unroll
        for (int d = 1; d < 16; d <<= 1) {
#pragma unroll
            for (int c = 0; c < 4; ++c) {
                const float u = __shfl_up_sync(0xffffffffu, p4[c], d);
                if (sl >= d) p4[c] += u;
            }
        }
        e0 = p4[0] - v4[0]; e1 = p4[1] - v4[1]; e2 = p4[2] - v4[2]; e3 = p4[3] - v4[3];
    }
    __syncthreads();   // B3: all s_p reads done; s_bp may overwrite s_p0

    if (hw < NBB) {
        const int bp = 49 * hw + 3 * sl;
        s_bp[bp] = make_float4(e0, e1, e2, e3);
        e0 += vb[0].x; e1 += vb[0].y; e2 += vb[0].z; e3 += vb[0].w;
        s_bp[bp + 1] = make_float4(e0, e1, e2, e3);
        e0 += vb[1].x; e1 += vb[1].y; e2 += vb[1].z; e3 += vb[1].w;
        s_bp[bp + 2] = make_float4(e0, e1, e2, e3);
        if (sl == 15) {
            e0 += vb[2].x; e1 += vb[2].y; e2 += vb[2].z; e3 += vb[2].w;
            s_bp[49 * hw + 48] = make_float4(e0, e1, e2, e3);
        }
    }
    __syncthreads();                                             // B4

    // ================= output pass: x re-read from gmem (L1 hit) =================
#pragma unroll
    for (int c0 = 0; c0 < 3; ++c0) {
        const int m = t + c0 * BK;
        if (m < WPB) {
            const int a = m / 48;
            const int o = m - 48 * a;
            const float4 P48 = s_bp[49 * a + 48];
            const float4 Po  = s_bp[49 * a + o];
            const float4 Q   = s_bp[49 * (a + 1) + o];
            const int n = n0 + m;
            if (n < N) {
                const float xr = x[3 * n];
                const float xg = x[3 * n + 1];
                const float xb = x[3 * n + 2];
                const float Br = P48.x - Po.x + Q.x;
                const float Bg = P48.y - Po.y + Q.y;
                const float Bb = P48.z - Po.z + Q.z;
                const float G  = P48.w - Po.w + Q.w;
                H[n] = fmaf(xr, Br, fmaf(xg, Bg, fmaf(xb, Bb, -G)));
            }
        }
    }
}

extern "C" void kernel_launch(void* const* d_in, const int* in_sizes, int n_in,
                              void* d_out, int out_size) {
    const float* x  = (const float*)d_in[0];   // rgbs [1, N, 3]
    const float* Wm = (const float*)d_in[1];   // W [2,3]
    // d_in[2] = bias: cancels exactly (h is window-mean-centered).

    const int N = in_sizes[0] / 3;
    const int K = N - WIN;
    float* H = (float*)d_out;

    const int grid = (N + WPB - 1) / WPB;
    pos_kernel<<<grid, BK>>>(x, Wm, H, N, K);
}

// round 12
// speedup vs baseline: 1.1000x; 1.1000x over previous
#include <cuda_runtime.h>

#define WIN   48
#define HALO  47
#define BK    128
#define WPB   288             // outputs per block (6 x 48)
#define NBB   7               // beta 48-blocks: betas i in [0, 336)
#define NMB   8               // moment 48-blocks: rows [0, 384)
#define TXR   384             // staged rows
#define XOFF  0.75f

// ---- shared layout ----
// [ s_p0 float4*NMB*49 | s_p1 float4*NMB*49 | s_p2 float*NMB*49 ]
//   s_bp (float4*NBB*49) aliases s_p0 after barrier B3.
// [ s_buf float*1156 ] (x staged at +3 float shift so base is 16B-aligned)
#define BUF_OFF  ((2 * NMB * 49 * 16 + NMB * 49 * 4 + 15) & ~15)
#define SMEM_TOT (BUF_OFF + 1156 * 4)

__device__ __forceinline__ float rcp_fast(float a) {
    float r; asm("rcp.approx.f32 %0, %1;" : "=f"(r) : "f"(a)); return r;
}
__device__ __forceinline__ float rsqrt_fast(float a) {
    float r; asm("rsqrt.approx.f32 %0, %1;" : "=f"(r) : "f"(a)); return r;
}

__global__ __launch_bounds__(BK, 10)
void pos_kernel(const float* __restrict__ x, const float* __restrict__ Wm,
                float* __restrict__ H, int N, int K) {
    __shared__ __align__(16) char smem[SMEM_TOT];
    float4* s_p0 = (float4*)smem;                      // {Sx,Sy,Sz,Mxx} prefixes
    float4* s_p1 = s_p0 + NMB * 49;                    // {Myy,Mzz,Mxy,Mxz}
    float*  s_p2 = (float*)(s_p1 + NMB * 49);          // Myz
    float4* s_bp = (float4*)smem;                      // beta prefixes (alias s_p0)
    float*  s_buf = (float*)(smem + BUF_OFF);          // centered x; row e at s_buf[3+e]

    const int t  = threadIdx.x;
    const int sl = t & 15;              // lane in half-warp segment
    const int hw = t >> 4;              // half-warp id 0..7
    const int n0 = blockIdx.x * WPB;
    const int kb = n0 - HALO;           // global row of local index 0

    const bool interior = (kb >= 1) && (kb + 386 <= N) && (kb + NBB * 48 <= K);

    if (interior) {
        // kb = 288b - 47 => kb ≡ 1 (mod 4) => 3kb-3 ≡ 0 (mod 4): aligned float4 base.
        const float4* x4 = (const float4*)(x + (3 * kb - 3));
        float4* b4 = (float4*)s_buf;
#pragma unroll
        for (int c0 = 0; c0 < 3; ++c0) {
            const int j = t + c0 * BK;
            if (j < 289) {
                float4 v = x4[j];
                v.x -= XOFF; v.y -= XOFF; v.z -= XOFF; v.w -= XOFF;
                b4[j] = v;
            }
        }
    } else {
        const int g0 = 3 * kb;
        for (int e = t; e < 3 * TXR; e += BK) {
            const int g = g0 + e;
            s_buf[3 + e] = (g >= 0 && g < 3 * N) ? (x[g] - XOFF) : 0.f;
        }
    }
    __syncthreads();                                             // B1

    const float W00 = Wm[0], W01 = Wm[1], W02 = Wm[2];
    const float W10 = Wm[3], W11 = Wm[4], W12 = Wm[5];
    const float r0 = W00 + W01 + W02;
    const float r1 = W10 + W11 + W12;
    // POS matrix fast path (reference fixes W = [[0,1,-1],[-2,1,1]])
    const bool fastW = (W00 == 0.f) && (W01 == 1.f) && (W02 == -1.f) &&
                       (W10 == -2.f) && (W11 == 1.f) && (W12 == 1.f);

    // ================= moment pass: local 48-block prefixes =================
    {
        const float* rp = s_buf + 3 + 3 * (48 * hw + 3 * sl);
        const float X0 = rp[0], Y0 = rp[1], Z0 = rp[2];
        const float X1 = rp[3], Y1 = rp[4], Z1 = rp[5];
        const float X2 = rp[6], Y2 = rp[7], Z2 = rp[8];

        float v[9];
        v[0] = X0 + X1 + X2; v[1] = Y0 + Y1 + Y2; v[2] = Z0 + Z1 + Z2;
        v[3] = fmaf(X2, X2, fmaf(X1, X1, X0 * X0));
        v[4] = fmaf(Y2, Y2, fmaf(Y1, Y1, Y0 * Y0));
        v[5] = fmaf(Z2, Z2, fmaf(Z1, Z1, Z0 * Z0));
        v[6] = fmaf(X2, Y2, fmaf(X1, Y1, X0 * Y0));
        v[7] = fmaf(X2, Z2, fmaf(X1, Z1, X0 * Z0));
        v[8] = fmaf(Y2, Z2, fmaf(Y1, Z1, Y0 * Z0));

        float p[9];
#pragma unroll
        for (int c = 0; c < 9; ++c) p[c] = v[c];
#pragma unroll
        for (int d = 1; d < 16; d <<= 1) {
#pragma unroll
            for (int c = 0; c < 9; ++c) {
                const float u = __shfl_up_sync(0xffffffffu, p[c], d);
                if (sl >= d) p[c] += u;
            }
        }

        float e[9];
#pragma unroll
        for (int c = 0; c < 9; ++c) e[c] = p[c] - v[c];
        const int bp = 49 * hw + 3 * sl;
        s_p0[bp] = make_float4(e[0], e[1], e[2], e[3]);
        s_p1[bp] = make_float4(e[4], e[5], e[6], e[7]);
        s_p2[bp] = e[8];
        e[0] += X0; e[1] += Y0; e[2] += Z0;
        e[3] = fmaf(X0, X0, e[3]); e[4] = fmaf(Y0, Y0, e[4]); e[5] = fmaf(Z0, Z0, e[5]);
        e[6] = fmaf(X0, Y0, e[6]); e[7] = fmaf(X0, Z0, e[7]); e[8] = fmaf(Y0, Z0, e[8]);
        s_p0[bp + 1] = make_float4(e[0], e[1], e[2], e[3]);
        s_p1[bp + 1] = make_float4(e[4], e[5], e[6], e[7]);
        s_p2[bp + 1] = e[8];
        e[0] += X1; e[1] += Y1; e[2] += Z1;
        e[3] = fmaf(X1, X1, e[3]); e[4] = fmaf(Y1, Y1, e[4]); e[5] = fmaf(Z1, Z1, e[5]);
        e[6] = fmaf(X1, Y1, e[6]); e[7] = fmaf(X1, Z1, e[7]); e[8] = fmaf(Y1, Z1, e[8]);
        s_p0[bp + 2] = make_float4(e[0], e[1], e[2], e[3]);
        s_p1[bp + 2] = make_float4(e[4], e[5], e[6], e[7]);
        s_p2[bp + 2] = e[8];
        if (sl == 15) {   // block total at position 48
            e[0] += X2; e[1] += Y2; e[2] += Z2;
            e[3] = fmaf(X2, X2, e[3]); e[4] = fmaf(Y2, Y2, e[4]); e[5] = fmaf(Z2, Z2, e[5]);
            e[6] = fmaf(X2, Y2, e[6]); e[7] = fmaf(X2, Z2, e[7]); e[8] = fmaf(Y2, Z2, e[8]);
            const int bt = 49 * hw + 48;
            s_p0[bt] = make_float4(e[0], e[1], e[2], e[3]);
            s_p1[bt] = make_float4(e[4], e[5], e[6], e[7]);
            s_p2[bt] = e[8];
        }
    }
    __syncthreads();                                             // B2

    // ========== beta pass: 3 betas/lane, held in regs + segmented scan ==========
    float4 vb[3];
    float e0, e1, e2, e3;
    {
        const int blkL = (hw < NBB) ? hw : (NBB - 1);   // clamp for loads only
        const int o0 = 3 * sl;
        const int lo = (kb < 0) ? -kb : 0;
        const int hi = (K - kb < NBB * 48) ? (K - kb) : (NBB * 48);

        const float4 T0 = s_p0[49 * blkL + 48];
        const float4 T1 = s_p1[49 * blkL + 48];
        const float  Tz = s_p2[49 * blkL + 48];

        float v4[4] = {0.f, 0.f, 0.f, 0.f};
#pragma unroll
        for (int r = 0; r < 3; ++r) {
            const int o = o0 + r;
            const float4 A0 = s_p0[49 * blkL + o];
            const float4 A1 = s_p1[49 * blkL + o];
            const float  Az = s_p2[49 * blkL + o];
            const float4 B0 = s_p0[49 * (blkL + 1) + o];
            const float4 B1 = s_p1[49 * (blkL + 1) + o];
            const float  Bz = s_p2[49 * (blkL + 1) + o];

            float4 out = make_float4(0.f, 0.f, 0.f, 0.f);
            const int i = 48 * hw + o;
            if (i >= lo && i < hi) {
                const float Sx  = T0.x - A0.x + B0.x;
                const float Sy  = T0.y - A0.y + B0.y;
                const float Sz  = T0.z - A0.z + B0.z;
                const float Mxx = T0.w - A0.w + B0.w;
                const float Myy = T1.x - A1.x + B1.x;
                const float Mzz = T1.y - A1.y + B1.y;
                const float Mxy = T1.z - A1.z + B1.z;
                const float Mxz = T1.w - A1.w + B1.w;
                const float Myz = Tz   - Az   + Bz;

                const float Sxp = Sx + 48.f * XOFF;   // = 48*m_r
                const float Syp = Sy + 48.f * XOFF;
                const float Szp = Sz + 48.f * XOFF;
                const float Pyz = Syp * Szp, Pxz = Sxp * Szp, Pxy = Sxp * Syp;
                const float inv = rcp_fast(Pyz * Sxp);   // 1/(Sxp*Syp*Szp)
                const float c48inv = 48.f * inv;

                if (fastW) {
                    // W = [[0,1,-1],[-2,1,1]]: a0=(0,Pxz,-Pxy), a1=(-2Pyz,Pxz,Pxy)
                    const float t1 = Pxz * Sy, t2 = Pxy * Sz, t3 = Pyz * Sx;
                    const float T0s = t1 - t2;
                    const float T1s = fmaf(-2.f, t3, t1 + t2);
                    const float Pxz2 = Pxz * Pxz, Pxy2 = Pxy * Pxy;
                    const float csh = fmaf(Pxz2, Myy, Pxy2 * Mzz);
                    const float dsh = 2.f * (Pxz * Pxy) * Myz;
                    const float q0 = (csh - dsh) - T0s * T0s * (1.f / 48.f);
                    const float P4 = 4.f * Pyz;
                    float q1 = csh + dsh;
                    q1 = fmaf(P4 * Pyz, Mxx, q1);
                    q1 = fmaf(-(P4 * Pxz), Mxy, q1);
                    q1 = fmaf(-(P4 * Pxy), Mxz, q1);
                    q1 -= T1s * T1s * (1.f / 48.f);
                    const float alpha = q0 * rsqrt_fast(q0 * q1);   // sqrt(q0/q1)
                    out.x = (-2.f * alpha) * (Pyz * c48inv);
                    out.y = (1.f + alpha) * (Pxz * c48inv);
                    out.z = (alpha - 1.f) * (Pxy * c48inv);
                    out.w = 0.f;                                    // r0 = r1 = 0
                } else {
                    const float a0r = W00 * Pyz, a0g = W01 * Pxz, a0b = W02 * Pxy;
                    const float a1r = W10 * Pyz, a1g = W11 * Pxz, a1b = W12 * Pxy;
                    const float T0s = a0r * Sx + a0g * Sy + a0b * Sz;
                    const float T1s = a1r * Sx + a1g * Sy + a1b * Sz;
                    const float q0 = a0r * a0r * Mxx + a0g * a0g * Myy + a0b * a0b * Mzz
                                   + 2.f * (a0r * a0g * Mxy + a0r * a0b * Mxz + a0g * a0b * Myz)
                                   - T0s * T0s * (1.f / 48.f);
                    const float q1 = a1r * a1r * Mxx + a1g * a1g * Myy + a1b * a1b * Mzz
                                   + 2.f * (a1r * a1g * Mxy + a1r * a1b * Mxz + a1g * a1b * Myz)
                                   - T1s * T1s * (1.f / 48.f);
                    const float alpha = q0 * rsqrt_fast(q0 * q1);
                    out.x = fmaf(alpha, W10, W00) * (Pyz * c48inv);
                    out.y = fmaf(alpha, W11, W01) * (Pxz * c48inv);
                    out.z = fmaf(alpha, W12, W02) * (Pxy * c48inv);
                    out.w = fmaf(alpha, r1, r0);
                }
            }
            vb[r] = out;
            v4[0] += out.x; v4[1] += out.y; v4[2] += out.z; v4[3] += out.w;
        }

        float p4[4];
#pragma unroll
        for (int c = 0; c < 4; ++c) p4[c] = v4[c];
#pragma unroll
        for (int d = 1; d < 16; d <<= 1) {
#pragma unroll
            for (int c = 0; c < 4; ++c) {
                const float u = __shfl_up_sync(0xffffffffu, p4[c], d);
                if (sl >= d) p4[c] += u;
            }
        }
        e0 = p4[0] - v4[0]; e1 = p4[1] - v4[1]; e2 = p4[2] - v4[2]; e3 = p4[3] - v4[3];
    }
    __syncthreads();   // B3: all s_p reads done; s_bp may overwrite s_p0

    if (hw < NBB) {
        const int bp = 49 * hw + 3 * sl;
        s_bp[bp] = make_float4(e0, e1, e2, e3);
        e0 += vb[0].x; e1 += vb[0].y; e2 += vb[0].z; e3 += vb[0].w;
        s_bp[bp + 1] = make_float4(e0, e1, e2, e3);
        e0 += vb[1].x; e1 += vb[1].y; e2 += vb[1].z; e3 += vb[1].w;
        s_bp[bp + 2] = make_float4(e0, e1, e2, e3);
        if (sl == 15) {
            e0 += vb[2].x; e1 += vb[2].y; e2 += vb[2].z; e3 += vb[2].w;
            s_bp[49 * hw + 48] = make_float4(e0, e1, e2, e3);
        }
    }
    __syncthreads();                                             // B4

    // ================= output pass =================
#pragma unroll
    for (int c0 = 0; c0 < 3; ++c0) {
        const int m = t + c0 * BK;
        if (m < WPB) {
            const int a = m / 48;
            const int o = m - 48 * a;
            const float4 P48 = s_bp[49 * a + 48];
            const float4 Po  = s_bp[49 * a + o];
            const float4 Q   = s_bp[49 * (a + 1) + o];
            const int n = n0 + m;
            if (n < N) {
                const float* xp = s_buf + 3 + 3 * (m + HALO);
                const float xr = xp[0] + XOFF;
                const float xg = xp[1] + XOFF;
                const float xb = xp[2] + XOFF;
                const float Br = P48.x - Po.x + Q.x;
                const float Bg = P48.y - Po.y + Q.y;
                const float Bb = P48.z - Po.z + Q.z;
                const float G  = P48.w - Po.w + Q.w;
                H[n] = fmaf(xr, Br, fmaf(xg, Bg, fmaf(xb, Bb, -G)));
            }
        }
    }
}

extern "C" void kernel_launch(void* const* d_in, const int* in_sizes, int n_in,
                              void* d_out, int out_size) {
    const float* x  = (const float*)d_in[0];   // rgbs [1, N, 3]
    const float* Wm = (const float*)d_in[1];   // W [2,3]
    // d_in[2] = bias: cancels exactly (h is window-mean-centered).

    const int N = in_sizes[0] / 3;
    const int K = N - WIN;
    float* H = (float*)d_out;

    const int grid = (N + WPB - 1) / WPB;
    pos_kernel<<<grid, BK>>>(x, Wm, H, N, K);
}

// round 13
// speedup vs baseline: 1.1866x; 1.0787x over previous
#include <cuda_runtime.h>

#define WIN   48
#define HALO  47
#define BK    96              // 3 warps = 6 half-warp segments
#define WPB   192             // outputs per block (4 x 48)
#define NBB   5               // beta 48-blocks: betas i in [0, 240)
#define NMB   6               // moment 48-blocks: rows [0, 288)
#define TXR   288             // staged rows
#define XOFF  0.75f

// ---- shared layout ----
// [ s_p0 float4*NMB*49 | s_p1 float4*NMB*49 | s_p2 float*NMB*49 ]
//   s_bp (float4*NBB*49) aliases s_p0 after barrier B3.
// [ s_buf float*(3*TXR+4) ] (x staged at +3 float shift so base is 16B-aligned)
#define BUF_OFF  ((2 * NMB * 49 * 16 + NMB * 49 * 4 + 15) & ~15)
#define SMEM_TOT (BUF_OFF + (3 * TXR + 4) * 4)

__device__ __forceinline__ float rcp_fast(float a) {
    float r; asm("rcp.approx.f32 %0, %1;" : "=f"(r) : "f"(a)); return r;
}
__device__ __forceinline__ float rsqrt_fast(float a) {
    float r; asm("rsqrt.approx.f32 %0, %1;" : "=f"(r) : "f"(a)); return r;
}

__global__ __launch_bounds__(BK, 14)
void pos_kernel(const float* __restrict__ x, const float* __restrict__ Wm,
                float* __restrict__ H, int N, int K) {
    __shared__ __align__(16) char smem[SMEM_TOT];
    float4* s_p0 = (float4*)smem;                      // {Sx,Sy,Sz,Mxx} prefixes
    float4* s_p1 = s_p0 + NMB * 49;                    // {Myy,Mzz,Mxy,Mxz}
    float*  s_p2 = (float*)(s_p1 + NMB * 49);          // Myz
    float4* s_bp = (float4*)smem;                      // beta prefixes (alias s_p0)
    float*  s_buf = (float*)(smem + BUF_OFF);          // centered x; row e at s_buf[3+e]

    const int t  = threadIdx.x;
    const int sl = t & 15;              // lane in half-warp segment
    const int hw = t >> 4;              // half-warp id 0..5
    const int n0 = blockIdx.x * WPB;
    const int kb = n0 - HALO;           // global row of local index 0

    const bool interior = (kb >= 1) && (kb + TXR + 2 <= N) && (kb + NBB * 48 <= K);

    if (interior) {
        // kb = 192b - 47 => 3kb-3 = 576b - 144 ≡ 0 (mod 4): aligned float4 base.
        const float4* x4 = (const float4*)(x + (3 * kb - 3));
        float4* b4 = (float4*)s_buf;
#pragma unroll
        for (int c0 = 0; c0 < 3; ++c0) {
            const int j = t + c0 * BK;
            if (j < 217) {     // ceil((3*TXR+3)/4)
                float4 v = x4[j];
                v.x -= XOFF; v.y -= XOFF; v.z -= XOFF; v.w -= XOFF;
                b4[j] = v;
            }
        }
    } else {
        const int g0 = 3 * kb;
        for (int e = t; e < 3 * TXR; e += BK) {
            const int g = g0 + e;
            s_buf[3 + e] = (g >= 0 && g < 3 * N) ? (x[g] - XOFF) : 0.f;
        }
    }
    __syncthreads();                                             // B1

    const float W00 = Wm[0], W01 = Wm[1], W02 = Wm[2];
    const float W10 = Wm[3], W11 = Wm[4], W12 = Wm[5];
    const float r0 = W00 + W01 + W02;
    const float r1 = W10 + W11 + W12;
    // POS matrix fast path (reference fixes W = [[0,1,-1],[-2,1,1]])
    const bool fastW = (W00 == 0.f) && (W01 == 1.f) && (W02 == -1.f) &&
                       (W10 == -2.f) && (W11 == 1.f) && (W12 == 1.f);

    // ================= moment pass: local 48-block prefixes (all 6 segments) =====
    {
        const float* rp = s_buf + 3 + 3 * (48 * hw + 3 * sl);
        const float X0 = rp[0], Y0 = rp[1], Z0 = rp[2];
        const float X1 = rp[3], Y1 = rp[4], Z1 = rp[5];
        const float X2 = rp[6], Y2 = rp[7], Z2 = rp[8];

        float v[9];
        v[0] = X0 + X1 + X2; v[1] = Y0 + Y1 + Y2; v[2] = Z0 + Z1 + Z2;
        v[3] = fmaf(X2, X2, fmaf(X1, X1, X0 * X0));
        v[4] = fmaf(Y2, Y2, fmaf(Y1, Y1, Y0 * Y0));
        v[5] = fmaf(Z2, Z2, fmaf(Z1, Z1, Z0 * Z0));
        v[6] = fmaf(X2, Y2, fmaf(X1, Y1, X0 * Y0));
        v[7] = fmaf(X2, Z2, fmaf(X1, Z1, X0 * Z0));
        v[8] = fmaf(Y2, Z2, fmaf(Y1, Z1, Y0 * Z0));

        float p[9];
#pragma unroll
        for (int c = 0; c < 9; ++c) p[c] = v[c];
#pragma unroll
        for (int d = 1; d < 16; d <<= 1) {
#pragma unroll
            for (int c = 0; c < 9; ++c) {
                const float u = __shfl_up_sync(0xffffffffu, p[c], d);
                if (sl >= d) p[c] += u;
            }
        }

        float e[9];
#pragma unroll
        for (int c = 0; c < 9; ++c) e[c] = p[c] - v[c];   // exclusive at chunk start
        const int bp = 49 * hw + 3 * sl;
        s_p0[bp] = make_float4(e[0], e[1], e[2], e[3]);
        s_p1[bp] = make_float4(e[4], e[5], e[6], e[7]);
        s_p2[bp] = e[8];
        e[0] += X0; e[1] += Y0; e[2] += Z0;
        e[3] = fmaf(X0, X0, e[3]); e[4] = fmaf(Y0, Y0, e[4]); e[5] = fmaf(Z0, Z0, e[5]);
        e[6] = fmaf(X0, Y0, e[6]); e[7] = fmaf(X0, Z0, e[7]); e[8] = fmaf(Y0, Z0, e[8]);
        s_p0[bp + 1] = make_float4(e[0], e[1], e[2], e[3]);
        s_p1[bp + 1] = make_float4(e[4], e[5], e[6], e[7]);
        s_p2[bp + 1] = e[8];
        e[0] += X1; e[1] += Y1; e[2] += Z1;
        e[3] = fmaf(X1, X1, e[3]); e[4] = fmaf(Y1, Y1, e[4]); e[5] = fmaf(Z1, Z1, e[5]);
        e[6] = fmaf(X1, Y1, e[6]); e[7] = fmaf(X1, Z1, e[7]); e[8] = fmaf(Y1, Z1, e[8]);
        s_p0[bp + 2] = make_float4(e[0], e[1], e[2], e[3]);
        s_p1[bp + 2] = make_float4(e[4], e[5], e[6], e[7]);
        s_p2[bp + 2] = e[8];
        if (sl == 15) {   // block total at position 48
            e[0] += X2; e[1] += Y2; e[2] += Z2;
            e[3] = fmaf(X2, X2, e[3]); e[4] = fmaf(Y2, Y2, e[4]); e[5] = fmaf(Z2, Z2, e[5]);
            e[6] = fmaf(X2, Y2, e[6]); e[7] = fmaf(X2, Z2, e[7]); e[8] = fmaf(Y2, Z2, e[8]);
            const int bt = 49 * hw + 48;
            s_p0[bt] = make_float4(e[0], e[1], e[2], e[3]);
            s_p1[bt] = make_float4(e[4], e[5], e[6], e[7]);
            s_p2[bt] = e[8];
        }
    }
    __syncthreads();                                             // B2

    // ========== beta pass: 3 betas/lane, held in regs + segmented scan ==========
    float4 vb[3];
    float e0, e1, e2, e3;
    {
        const int blkL = (hw < NBB) ? hw : (NBB - 1);   // clamp for loads only
        const int o0 = 3 * sl;
        const int lo = (kb < 0) ? -kb : 0;
        const int hi = (K - kb < NBB * 48) ? (K - kb) : (NBB * 48);

        const float4 T0 = s_p0[49 * blkL + 48];
        const float4 T1 = s_p1[49 * blkL + 48];
        const float  Tz = s_p2[49 * blkL + 48];

        float v4[4] = {0.f, 0.f, 0.f, 0.f};
#pragma unroll
        for (int r = 0; r < 3; ++r) {
            const int o = o0 + r;
            const float4 A0 = s_p0[49 * blkL + o];
            const float4 A1 = s_p1[49 * blkL + o];
            const float  Az = s_p2[49 * blkL + o];
            const float4 B0 = s_p0[49 * (blkL + 1) + o];
            const float4 B1 = s_p1[49 * (blkL + 1) + o];
            const float  Bz = s_p2[49 * (blkL + 1) + o];

            float4 out = make_float4(0.f, 0.f, 0.f, 0.f);
            const int i = 48 * hw + o;
            if (i >= lo && i < hi) {
                const float Sx  = T0.x - A0.x + B0.x;
                const float Sy  = T0.y - A0.y + B0.y;
                const float Sz  = T0.z - A0.z + B0.z;
                const float Mxx = T0.w - A0.w + B0.w;
                const float Myy = T1.x - A1.x + B1.x;
                const float Mzz = T1.y - A1.y + B1.y;
                const float Mxy = T1.z - A1.z + B1.z;
                const float Mxz = T1.w - A1.w + B1.w;
                const float Myz = Tz   - Az   + Bz;

                const float Sxp = Sx + 48.f * XOFF;   // = 48*m_r
                const float Syp = Sy + 48.f * XOFF;
                const float Szp = Sz + 48.f * XOFF;
                const float Pyz = Syp * Szp, Pxz = Sxp * Szp, Pxy = Sxp * Syp;
                const float inv = rcp_fast(Pyz * Sxp);   // 1/(Sxp*Syp*Szp)
                const float c48inv = 48.f * inv;

                if (fastW) {
                    // W = [[0,1,-1],[-2,1,1]]: a0=(0,Pxz,-Pxy), a1=(-2Pyz,Pxz,Pxy)
                    const float t1 = Pxz * Sy, t2 = Pxy * Sz, t3 = Pyz * Sx;
                    const float T0s = t1 - t2;
                    const float T1s = fmaf(-2.f, t3, t1 + t2);
                    const float Pxz2 = Pxz * Pxz, Pxy2 = Pxy * Pxy;
                    const float csh = fmaf(Pxz2, Myy, Pxy2 * Mzz);
                    const float dsh = 2.f * (Pxz * Pxy) * Myz;
                    const float q0 = (csh - dsh) - T0s * T0s * (1.f / 48.f);
                    const float P4 = 4.f * Pyz;
                    float q1 = csh + dsh;
                    q1 = fmaf(P4 * Pyz, Mxx, q1);
                    q1 = fmaf(-(P4 * Pxz), Mxy, q1);
                    q1 = fmaf(-(P4 * Pxy), Mxz, q1);
                    q1 -= T1s * T1s * (1.f / 48.f);
                    const float alpha = q0 * rsqrt_fast(q0 * q1);   // sqrt(q0/q1)
                    out.x = (-2.f * alpha) * (Pyz * c48inv);
                    out.y = (1.f + alpha) * (Pxz * c48inv);
                    out.z = (alpha - 1.f) * (Pxy * c48inv);
                    out.w = 0.f;                                    // r0 = r1 = 0
                } else {
                    const float a0r = W00 * Pyz, a0g = W01 * Pxz, a0b = W02 * Pxy;
                    const float a1r = W10 * Pyz, a1g = W11 * Pxz, a1b = W12 * Pxy;
                    const float T0s = a0r * Sx + a0g * Sy + a0b * Sz;
                    const float T1s = a1r * Sx + a1g * Sy + a1b * Sz;
                    const float q0 = a0r * a0r * Mxx + a0g * a0g * Myy + a0b * a0b * Mzz
                                   + 2.f * (a0r * a0g * Mxy + a0r * a0b * Mxz + a0g * a0b * Myz)
                                   - T0s * T0s * (1.f / 48.f);
                    const float q1 = a1r * a1r * Mxx + a1g * a1g * Myy + a1b * a1b * Mzz
                                   + 2.f * (a1r * a1g * Mxy + a1r * a1b * Mxz + a1g * a1b * Myz)
                                   - T1s * T1s * (1.f / 48.f);
                    const float alpha = q0 * rsqrt_fast(q0 * q1);
                    out.x = fmaf(alpha, W10, W00) * (Pyz * c48inv);
                    out.y = fmaf(alpha, W11, W01) * (Pxz * c48inv);
                    out.z = fmaf(alpha, W12, W02) * (Pxy * c48inv);
                    out.w = fmaf(alpha, r1, r0);
                }
            }
            vb[r] = out;
            v4[0] += out.x; v4[1] += out.y; v4[2] += out.z; v4[3] += out.w;
        }

        float p4[4];
#pragma unroll
        for (int c = 0; c < 4; ++c) p4[c] = v4[c];
#pragma unroll
        for (int d = 1; d < 16; d <<= 1) {
#pragma unroll
            for (int c = 0; c < 4; ++c) {
                const float u = __shfl_up_sync(0xffffffffu, p4[c], d);
                if (sl >= d) p4[c] += u;
            }
        }
        e0 = p4[0] - v4[0]; e1 = p4[1] - v4[1]; e2 = p4[2] - v4[2]; e3 = p4[3] - v4[3];
    }
    __syncthreads();   // B3: all s_p reads done; s_bp may overwrite s_p0

    if (hw < NBB) {
        const int bp = 49 * hw + 3 * sl;
        s_bp[bp] = make_float4(e0, e1, e2, e3);
        e0 += vb[0].x; e1 += vb[0].y; e2 += vb[0].z; e3 += vb[0].w;
        s_bp[bp + 1] = make_float4(e0, e1, e2, e3);
        e0 += vb[1].x; e1 += vb[1].y; e2 += vb[1].z; e3 += vb[1].w;
        s_bp[bp + 2] = make_float4(e0, e1, e2, e3);
        if (sl == 15) {
            e0 += vb[2].x; e1 += vb[2].y; e2 += vb[2].z; e3 += vb[2].w;
            s_bp[49 * hw + 48] = make_float4(e0, e1, e2, e3);
        }
    }
    __syncthreads();                                             // B4

    // ================= output pass (2 outputs/thread, no m guard needed) =========
#pragma unroll
    for (int c0 = 0; c0 < 2; ++c0) {
        const int m = t + c0 * BK;          // m < 192 = WPB always
        const int a = m / 48;
        const int o = m - 48 * a;
        const float4 P48 = s_bp[49 * a + 48];
        const float4 Po  = s_bp[49 * a + o];
        const float4 Q   = s_bp[49 * (a + 1) + o];
        const int n = n0 + m;
        if (n < N) {
            const float* xp = s_buf + 3 + 3 * (m + HALO);
            const float xr = xp[0] + XOFF;
            const float xg = xp[1] + XOFF;
            const float xb = xp[2] + XOFF;
            const float Br = P48.x - Po.x + Q.x;
            const float Bg = P48.y - Po.y + Q.y;
            const float Bb = P48.z - Po.z + Q.z;
            const float G  = P48.w - Po.w + Q.w;
            H[n] = fmaf(xr, Br, fmaf(xg, Bg, fmaf(xb, Bb, -G)));
        }
    }
}

extern "C" void kernel_launch(void* const* d_in, const int* in_sizes, int n_in,
                              void* d_out, int out_size) {
    const float* x  = (const float*)d_in[0];   // rgbs [1, N, 3]
    const float* Wm = (const float*)d_in[1];   // W [2,3]
    // d_in[2] = bias: cancels exactly (h is window-mean-centered).

    const int N = in_sizes[0] / 3;
    const int K = N - WIN;
    float* H = (float*)d_out;

    const int grid = (N + WPB - 1) / WPB;
    pos_kernel<<<grid, BK>>>(x, Wm, H, N, K);
}

// round 15
// speedup vs baseline: 1.2113x; 1.0208x over previous
#include <cuda_runtime.h>

#define WIN   48
#define HALO  47
#define BK    128
#define WPB   288             // outputs per block (6 x 48)
#define NBB   7               // beta 48-blocks: betas i in [0, 336)
#define NMB   8               // moment 48-blocks: rows [0, 384)
#define TXR   384             // staged rows
#define XOFF  0.75f

// ---- shared layout (NO aliasing: s_bp is its own region, so no barrier is
// needed between the beta pass's s_p reads and the s_bp writes) ----
#define SP_BYTES (2 * NMB * 49 * 16 + NMB * 49 * 4)    // 14112, 16B-multiple
#define BP_OFF   SP_BYTES
#define BUF_OFF  (BP_OFF + NBB * 49 * 16)              // 19600, 16B-multiple
#define SMEM_TOT (BUF_OFF + 1156 * 4)                  // 24224 B

__device__ __forceinline__ float rcp_fast(float a) {
    float r; asm("rcp.approx.f32 %0, %1;" : "=f"(r) : "f"(a)); return r;
}
__device__ __forceinline__ float rsqrt_fast(float a) {
    float r; asm("rsqrt.approx.f32 %0, %1;" : "=f"(r) : "f"(a)); return r;
}

__global__ __launch_bounds__(BK, 9)
void pos_kernel(const float* __restrict__ x, const float* __restrict__ Wm,
                float* __restrict__ H, int N, int K) {
    __shared__ __align__(16) char smem[SMEM_TOT];
    float4* s_p0 = (float4*)smem;                      // {Sx,Sy,Sz,Mxx} prefixes
    float4* s_p1 = s_p0 + NMB * 49;                    // {Myy,Mzz,Mxy,Mxz}
    float*  s_p2 = (float*)(s_p1 + NMB * 49);          // Myz
    float4* s_bp = (float4*)(smem + BP_OFF);           // beta prefixes (own region)
    float*  s_buf = (float*)(smem + BUF_OFF);          // centered x; row e at s_buf[3+e]

    const int t    = threadIdx.x;
    const int sl   = t & 15;            // lane in half-warp segment
    const int hw   = t >> 4;            // half-warp id 0..7
    const int wid  = t >> 5;            // warp id 0..3
    const int lane = t & 31;
    const int n0 = blockIdx.x * WPB;
    const int kb = n0 - HALO;           // global row of local index 0

    const bool interior = (kb >= 1) && (kb + 386 <= N) && (kb + NBB * 48 <= K);

    // ---- warp-local staging: warp w's moment reads span floats
    // [288w+3, 288w+290], i.e. float4 j in [72w, 72w+72] INCLUSIVE. Each warp
    // stages 73 float4s [72w, 72w+73); boundary j=72(w+1) is written by both
    // warp w and w+1 with bit-identical values (same gmem load, same XOFF),
    // so the overlap is deterministic. Cross-warp readers are behind B2. ----
    if (interior) {
        // kb = 288b - 47 => 3kb-3 ≡ 0 (mod 4): aligned float4 base.
        const float4* x4 = (const float4*)(x + (3 * kb - 3));
        float4* b4 = (float4*)s_buf;
        int j = 72 * wid + lane;
        {   float4 v = x4[j];
            v.x -= XOFF; v.y -= XOFF; v.z -= XOFF; v.w -= XOFF; b4[j] = v; }
        j += 32;
        {   float4 v = x4[j];
            v.x -= XOFF; v.y -= XOFF; v.z -= XOFF; v.w -= XOFF; b4[j] = v; }
        if (lane < 9) {   // third round: j in [72w+64, 72w+72]
            j = 72 * wid + 64 + lane;
            float4 v = x4[j];
            v.x -= XOFF; v.y -= XOFF; v.z -= XOFF; v.w -= XOFF; b4[j] = v;
        }
    } else {
        // scalar path: warp w stages s_buf[3+e], e in [288w, 288w+288) —
        // exactly the float range [288w+3, 288w+291) its own segments read.
        const int g0 = 3 * kb;
#pragma unroll
        for (int r = 0; r < 9; ++r) {
            const int e = 288 * wid + lane + 32 * r;
            const int g = g0 + e;
            s_buf[3 + e] = (g >= 0 && g < 3 * N) ? (x[g] - XOFF) : 0.f;
        }
    }
    __syncwarp();                                      // staging visible warp-locally

    const float W00 = Wm[0], W01 = Wm[1], W02 = Wm[2];
    const float W10 = Wm[3], W11 = Wm[4], W12 = Wm[5];
    const float r0 = W00 + W01 + W02;
    const float r1 = W10 + W11 + W12;
    // POS matrix fast path (reference fixes W = [[0,1,-1],[-2,1,1]])
    const bool fastW = (W00 == 0.f) && (W01 == 1.f) && (W02 == -1.f) &&
                       (W10 == -2.f) && (W11 == 1.f) && (W12 == 1.f);

    // ============ moment pass: local 48-block prefixes (own warp's rows) ========
    {
        const float* rp = s_buf + 3 + 3 * (48 * hw + 3 * sl);
        const float X0 = rp[0], Y0 = rp[1], Z0 = rp[2];
        const float X1 = rp[3], Y1 = rp[4], Z1 = rp[5];
        const float X2 = rp[6], Y2 = rp[7], Z2 = rp[8];

        float v[9];
        v[0] = X0 + X1 + X2; v[1] = Y0 + Y1 + Y2; v[2] = Z0 + Z1 + Z2;
        v[3] = fmaf(X2, X2, fmaf(X1, X1, X0 * X0));
        v[4] = fmaf(Y2, Y2, fmaf(Y1, Y1, Y0 * Y0));
        v[5] = fmaf(Z2, Z2, fmaf(Z1, Z1, Z0 * Z0));
        v[6] = fmaf(X2, Y2, fmaf(X1, Y1, X0 * Y0));
        v[7] = fmaf(X2, Z2, fmaf(X1, Z1, X0 * Z0));
        v[8] = fmaf(Y2, Z2, fmaf(Y1, Z1, Y0 * Z0));

        float p[9];
#pragma unroll
        for (int c = 0; c < 9; ++c) p[c] = v[c];
#pragma unroll
        for (int d = 1; d < 16; d <<= 1) {
#pragma unroll
            for (int c = 0; c < 9; ++c) {
                const float u = __shfl_up_sync(0xffffffffu, p[c], d);
                if (sl >= d) p[c] += u;
            }
        }

        float e[9];
#pragma unroll
        for (int c = 0; c < 9; ++c) e[c] = p[c] - v[c];   // exclusive at chunk start
        const int bp = 49 * hw + 3 * sl;
        s_p0[bp] = make_float4(e[0], e[1], e[2], e[3]);
        s_p1[bp] = make_float4(e[4], e[5], e[6], e[7]);
        s_p2[bp] = e[8];
        e[0] += X0; e[1] += Y0; e[2] += Z0;
        e[3] = fmaf(X0, X0, e[3]); e[4] = fmaf(Y0, Y0, e[4]); e[5] = fmaf(Z0, Z0, e[5]);
        e[6] = fmaf(X0, Y0, e[6]); e[7] = fmaf(X0, Z0, e[7]); e[8] = fmaf(Y0, Z0, e[8]);
        s_p0[bp + 1] = make_float4(e[0], e[1], e[2], e[3]);
        s_p1[bp + 1] = make_float4(e[4], e[5], e[6], e[7]);
        s_p2[bp + 1] = e[8];
        e[0] += X1; e[1] += Y1; e[2] += Z1;
        e[3] = fmaf(X1, X1, e[3]); e[4] = fmaf(Y1, Y1, e[4]); e[5] = fmaf(Z1, Z1, e[5]);
        e[6] = fmaf(X1, Y1, e[6]); e[7] = fmaf(X1, Z1, e[7]); e[8] = fmaf(Y1, Z1, e[8]);
        s_p0[bp + 2] = make_float4(e[0], e[1], e[2], e[3]);
        s_p1[bp + 2] = make_float4(e[4], e[5], e[6], e[7]);
        s_p2[bp + 2] = e[8];
        if (sl == 15) {   // block total at position 48
            e[0] += X2; e[1] += Y2; e[2] += Z2;
            e[3] = fmaf(X2, X2, e[3]); e[4] = fmaf(Y2, Y2, e[4]); e[5] = fmaf(Z2, Z2, e[5]);
            e[6] = fmaf(X2, Y2, e[6]); e[7] = fmaf(X2, Z2, e[7]); e[8] = fmaf(Y2, Z2, e[8]);
            const int bt = 49 * hw + 48;
            s_p0[bt] = make_float4(e[0], e[1], e[2], e[3]);
            s_p1[bt] = make_float4(e[4], e[5], e[6], e[7]);
            s_p2[bt] = e[8];
        }
    }
    __syncthreads();                                   // B2: moments visible block-wide

    // ========== beta pass: 3 betas/lane, regs + segmented scan, store s_bp ======
    {
        const int blkL = (hw < NBB) ? hw : (NBB - 1);   // clamp for loads only
        const int o0 = 3 * sl;
        const int lo = (kb < 0) ? -kb : 0;
        const int hi = (K - kb < NBB * 48) ? (K - kb) : (NBB * 48);

        const float4 T0 = s_p0[49 * blkL + 48];
        const float4 T1 = s_p1[49 * blkL + 48];
        const float  Tz = s_p2[49 * blkL + 48];

        float4 vb[3];
        float v4[4] = {0.f, 0.f, 0.f, 0.f};
#pragma unroll
        for (int r = 0; r < 3; ++r) {
            const int o = o0 + r;
            const float4 A0 = s_p0[49 * blkL + o];
            const float4 A1 = s_p1[49 * blkL + o];
            const float  Az = s_p2[49 * blkL + o];
            const float4 B0 = s_p0[49 * (blkL + 1) + o];
            const float4 B1 = s_p1[49 * (blkL + 1) + o];
            const float  Bz = s_p2[49 * (blkL + 1) + o];

            float4 out = make_float4(0.f, 0.f, 0.f, 0.f);
            const int i = 48 * hw + o;
            if (i >= lo && i < hi) {
                const float Sx  = T0.x - A0.x + B0.x;
                const float Sy  = T0.y - A0.y + B0.y;
                const float Sz  = T0.z - A0.z + B0.z;
                const float Mxx = T0.w - A0.w + B0.w;
                const float Myy = T1.x - A1.x + B1.x;
                const float Mzz = T1.y - A1.y + B1.y;
                const float Mxy = T1.z - A1.z + B1.z;
                const float Mxz = T1.w - A1.w + B1.w;
                const float Myz = Tz   - Az   + Bz;

                const float Sxp = Sx + 48.f * XOFF;   // = 48*m_r
                const float Syp = Sy + 48.f * XOFF;
                const float Szp = Sz + 48.f * XOFF;
                const float Pyz = Syp * Szp, Pxz = Sxp * Szp, Pxy = Sxp * Syp;
                const float inv = rcp_fast(Pyz * Sxp);   // 1/(Sxp*Syp*Szp)
                const float c48inv = 48.f * inv;

                if (fastW) {
                    // W = [[0,1,-1],[-2,1,1]]: a0=(0,Pxz,-Pxy), a1=(-2Pyz,Pxz,Pxy)
                    const float t1 = Pxz * Sy, t2 = Pxy * Sz, t3 = Pyz * Sx;
                    const float T0s = t1 - t2;
                    const float T1s = fmaf(-2.f, t3, t1 + t2);
                    const float Pxz2 = Pxz * Pxz, Pxy2 = Pxy * Pxy;
                    const float csh = fmaf(Pxz2, Myy, Pxy2 * Mzz);
                    const float dsh = 2.f * (Pxz * Pxy) * Myz;
                    const float q0 = (csh - dsh) - T0s * T0s * (1.f / 48.f);
                    const float P4 = 4.f * Pyz;
                    float q1 = csh + dsh;
                    q1 = fmaf(P4 * Pyz, Mxx, q1);
                    q1 = fmaf(-(P4 * Pxz), Mxy, q1);
                    q1 = fmaf(-(P4 * Pxy), Mxz, q1);
                    q1 -= T1s * T1s * (1.f / 48.f);
                    const float alpha = q0 * rsqrt_fast(q0 * q1);   // sqrt(q0/q1)
                    out.x = (-2.f * alpha) * (Pyz * c48inv);
                    out.y = (1.f + alpha) * (Pxz * c48inv);
                    out.z = (alpha - 1.f) * (Pxy * c48inv);
                    out.w = 0.f;                                    // r0 = r1 = 0
                } else {
                    const float a0r = W00 * Pyz, a0g = W01 * Pxz, a0b = W02 * Pxy;
                    const float a1r = W10 * Pyz, a1g = W11 * Pxz, a1b = W12 * Pxy;
                    const float T0s = a0r * Sx + a0g * Sy + a0b * Sz;
                    const float T1s = a1r * Sx + a1g * Sy + a1b * Sz;
                    const float q0 = a0r * a0r * Mxx + a0g * a0g * Myy + a0b * a0b * Mzz
                                   + 2.f * (a0r * a0g * Mxy + a0r * a0b * Mxz + a0g * a0b * Myz)
                                   - T0s * T0s * (1.f / 48.f);
                    const float q1 = a1r * a1r * Mxx + a1g * a1g * Myy + a1b * a1b * Mzz
                                   + 2.f * (a1r * a1g * Mxy + a1r * a1b * Mxz + a1g * a1b * Myz)
                                   - T1s * T1s * (1.f / 48.f);
                    const float alpha = q0 * rsqrt_fast(q0 * q1);
                    out.x = fmaf(alpha, W10, W00) * (Pyz * c48inv);
                    out.y = fmaf(alpha, W11, W01) * (Pxz * c48inv);
                    out.z = fmaf(alpha, W12, W02) * (Pxy * c48inv);
                    out.w = fmaf(alpha, r1, r0);
                }
            }
            vb[r] = out;
            v4[0] += out.x; v4[1] += out.y; v4[2] += out.z; v4[3] += out.w;
        }

        float p4[4];
#pragma unroll
        for (int c = 0; c < 4; ++c) p4[c] = v4[c];
#pragma unroll
        for (int d = 1; d < 16; d <<= 1) {
#pragma unroll
            for (int c = 0; c < 4; ++c) {
                const float u = __shfl_up_sync(0xffffffffu, p4[c], d);
                if (sl >= d) p4[c] += u;
            }
        }
        // s_bp is a separate region: store immediately, no intervening barrier
        if (hw < NBB) {
            float e0 = p4[0] - v4[0], e1 = p4[1] - v4[1];
            float e2 = p4[2] - v4[2], e3 = p4[3] - v4[3];
            const int bp = 49 * hw + o0;
            s_bp[bp] = make_float4(e0, e1, e2, e3);
            e0 += vb[0].x; e1 += vb[0].y; e2 += vb[0].z; e3 += vb[0].w;
            s_bp[bp + 1] = make_float4(e0, e1, e2, e3);
            e0 += vb[1].x; e1 += vb[1].y; e2 += vb[1].z; e3 += vb[1].w;
            s_bp[bp + 2] = make_float4(e0, e1, e2, e3);
            if (sl == 15) {
                e0 += vb[2].x; e1 += vb[2].y; e2 += vb[2].z; e3 += vb[2].w;
                s_bp[49 * hw + 48] = make_float4(e0, e1, e2, e3);
            }
        }
    }
    __syncthreads();                                   // B4: beta prefixes visible

    // ================= output pass =================
#pragma unroll
    for (int c0 = 0; c0 < 3; ++c0) {
        const int m = t + c0 * BK;
        if (m < WPB) {
            const int a = m / 48;
            const int o = m - 48 * a;
            const float4 P48 = s_bp[49 * a + 48];
            const float4 Po  = s_bp[49 * a + o];
            const float4 Q   = s_bp[49 * (a + 1) + o];
            const int n = n0 + m;
            if (n < N) {
                const float* xp = s_buf + 3 + 3 * (m + HALO);
                const float xr = xp[0] + XOFF;
                const float xg = xp[1] + XOFF;
                const float xb = xp[2] + XOFF;
                const float Br = P48.x - Po.x + Q.x;
                const float Bg = P48.y - Po.y + Q.y;
                const float Bb = P48.z - Po.z + Q.z;
                const float G  = P48.w - Po.w + Q.w;
                H[n] = fmaf(xr, Br, fmaf(xg, Bg, fmaf(xb, Bb, -G)));
            }
        }
    }
}

extern "C" void kernel_launch(void* const* d_in, const int* in_sizes, int n_in,
                              void* d_out, int out_size) {
    const float* x  = (const float*)d_in[0];   // rgbs [1, N, 3]
    const float* Wm = (const float*)d_in[1];   // W [2,3]
    // d_in[2] = bias: cancels exactly (h is window-mean-centered).

    const int N = in_sizes[0] / 3;
    const int K = N - WIN;
    float* H = (float*)d_out;

    const int grid = (N + WPB - 1) / WPB;
    pos_kernel<<<grid, BK>>>(x, Wm, H, N, K);
}

// round 16
// speedup vs baseline: 1.2149x; 1.0030x over previous
#include <cuda_runtime.h>

#define WIN   48
#define HALO  47
#define BK    160             // 5 warps = 10 half-warp segments
#define WPB   384             // outputs per block (8 x 48)
#define NBB   9               // beta 48-blocks: betas i in [0, 432)
#define NMB   10              // moment 48-blocks: rows [0, 480)
#define TXR   480             // staged rows
#define XOFF  0.75f

// ---- shared layout (NO aliasing: s_bp is its own region) ----
#define SP_BYTES ((2 * NMB * 49 * 16 + NMB * 49 * 4 + 15) & ~15)   // 17648
#define BP_OFF   SP_BYTES
#define BUF_OFF  (BP_OFF + NBB * 49 * 16)                          // 24704
#define SMEM_TOT (BUF_OFF + 1444 * 4)                              // 30480 B

__device__ __forceinline__ float rcp_fast(float a) {
    float r; asm("rcp.approx.f32 %0, %1;" : "=f"(r) : "f"(a)); return r;
}
__device__ __forceinline__ float rsqrt_fast(float a) {
    float r; asm("rsqrt.approx.f32 %0, %1;" : "=f"(r) : "f"(a)); return r;
}

__global__ __launch_bounds__(BK, 7)
void pos_kernel(const float* __restrict__ x, const float* __restrict__ Wm,
                float* __restrict__ H, int N, int K) {
    __shared__ __align__(16) char smem[SMEM_TOT];
    float4* s_p0 = (float4*)smem;                      // {Sx,Sy,Sz,Mxx} prefixes
    float4* s_p1 = s_p0 + NMB * 49;                    // {Myy,Mzz,Mxy,Mxz}
    float*  s_p2 = (float*)(s_p1 + NMB * 49);          // Myz
    float4* s_bp = (float4*)(smem + BP_OFF);           // beta prefixes (own region)
    float*  s_buf = (float*)(smem + BUF_OFF);          // centered x; row e at s_buf[3+e]

    const int t    = threadIdx.x;
    const int sl   = t & 15;            // lane in half-warp segment
    const int hw   = t >> 4;            // half-warp id 0..9
    const int wid  = t >> 5;            // warp id 0..4
    const int lane = t & 31;
    const int n0 = blockIdx.x * WPB;
    const int kb = n0 - HALO;           // global row of local index 0

    const bool interior = (kb >= 1) && (kb + 482 <= N) && (kb + NBB * 48 <= K);

    // ---- warp-local staging: warp w's moment reads (segments 2w, 2w+1 = rows
    // [96w, 96w+96)) span float4 j in [72w, 72w+72] INCLUSIVE. Each warp stages
    // 73 float4s [72w, 72w+73); the boundary j=72(w+1) is written by both warps
    // with bit-identical values (same gmem load, same XOFF). Cross-warp readers
    // (beta B-reads, output pass) are behind B2/B4. ----
    if (interior) {
        // kb = 384b - 47 => kb ≡ 1 (mod 4) => 3kb-3 ≡ 0 (mod 4): aligned base.
        const float4* x4 = (const float4*)(x + (3 * kb - 3));
        float4* b4 = (float4*)s_buf;
        int j = 72 * wid + lane;
        {   float4 v = x4[j];
            v.x -= XOFF; v.y -= XOFF; v.z -= XOFF; v.w -= XOFF; b4[j] = v; }
        j += 32;
        {   float4 v = x4[j];
            v.x -= XOFF; v.y -= XOFF; v.z -= XOFF; v.w -= XOFF; b4[j] = v; }
        if (lane < 9) {   // third round: j in [72w+64, 72w+72]
            j = 72 * wid + 64 + lane;
            float4 v = x4[j];
            v.x -= XOFF; v.y -= XOFF; v.z -= XOFF; v.w -= XOFF; b4[j] = v;
        }
    } else {
        // scalar path: warp w stages s_buf[3+e], e in [288w, 288w+288) —
        // exactly the float range [288w+3, 288w+291) its own segments read.
        const int g0 = 3 * kb;
#pragma unroll
        for (int r = 0; r < 9; ++r) {
            const int e = 288 * wid + lane + 32 * r;
            const int g = g0 + e;
            s_buf[3 + e] = (g >= 0 && g < 3 * N) ? (x[g] - XOFF) : 0.f;
        }
    }
    __syncwarp();                                      // staging visible warp-locally

    const float W00 = Wm[0], W01 = Wm[1], W02 = Wm[2];
    const float W10 = Wm[3], W11 = Wm[4], W12 = Wm[5];
    const float r0 = W00 + W01 + W02;
    const float r1 = W10 + W11 + W12;
    // POS matrix fast path (reference fixes W = [[0,1,-1],[-2,1,1]])
    const bool fastW = (W00 == 0.f) && (W01 == 1.f) && (W02 == -1.f) &&
                       (W10 == -2.f) && (W11 == 1.f) && (W12 == 1.f);

    // ============ moment pass: local 48-block prefixes (own warp's rows) ========
    {
        const float* rp = s_buf + 3 + 3 * (48 * hw + 3 * sl);
        const float X0 = rp[0], Y0 = rp[1], Z0 = rp[2];
        const float X1 = rp[3], Y1 = rp[4], Z1 = rp[5];
        const float X2 = rp[6], Y2 = rp[7], Z2 = rp[8];

        float v[9];
        v[0] = X0 + X1 + X2; v[1] = Y0 + Y1 + Y2; v[2] = Z0 + Z1 + Z2;
        v[3] = fmaf(X2, X2, fmaf(X1, X1, X0 * X0));
        v[4] = fmaf(Y2, Y2, fmaf(Y1, Y1, Y0 * Y0));
        v[5] = fmaf(Z2, Z2, fmaf(Z1, Z1, Z0 * Z0));
        v[6] = fmaf(X2, Y2, fmaf(X1, Y1, X0 * Y0));
        v[7] = fmaf(X2, Z2, fmaf(X1, Z1, X0 * Z0));
        v[8] = fmaf(Y2, Z2, fmaf(Y1, Z1, Y0 * Z0));

        float p[9];
#pragma unroll
        for (int c = 0; c < 9; ++c) p[c] = v[c];
#pragma unroll
        for (int d = 1; d < 16; d <<= 1) {
#pragma unroll
            for (int c = 0; c < 9; ++c) {
                const float u = __shfl_up_sync(0xffffffffu, p[c], d);
                if (sl >= d) p[c] += u;
            }
        }

        float e[9];
#pragma unroll
        for (int c = 0; c < 9; ++c) e[c] = p[c] - v[c];   // exclusive at chunk start
        const int bp = 49 * hw + 3 * sl;
        s_p0[bp] = make_float4(e[0], e[1], e[2], e[3]);
        s_p1[bp] = make_float4(e[4], e[5], e[6], e[7]);
        s_p2[bp] = e[8];
        e[0] += X0; e[1] += Y0; e[2] += Z0;
        e[3] = fmaf(X0, X0, e[3]); e[4] = fmaf(Y0, Y0, e[4]); e[5] = fmaf(Z0, Z0, e[5]);
        e[6] = fmaf(X0, Y0, e[6]); e[7] = fmaf(X0, Z0, e[7]); e[8] = fmaf(Y0, Z0, e[8]);
        s_p0[bp + 1] = make_float4(e[0], e[1], e[2], e[3]);
        s_p1[bp + 1] = make_float4(e[4], e[5], e[6], e[7]);
        s_p2[bp + 1] = e[8];
        e[0] += X1; e[1] += Y1; e[2] += Z1;
        e[3] = fmaf(X1, X1, e[3]); e[4] = fmaf(Y1, Y1, e[4]); e[5] = fmaf(Z1, Z1, e[5]);
        e[6] = fmaf(X1, Y1, e[6]); e[7] = fmaf(X1, Z1, e[7]); e[8] = fmaf(Y1, Z1, e[8]);
        s_p0[bp + 2] = make_float4(e[0], e[1], e[2], e[3]);
        s_p1[bp + 2] = make_float4(e[4], e[5], e[6], e[7]);
        s_p2[bp + 2] = e[8];
        if (sl == 15) {   // block total at position 48
            e[0] += X2; e[1] += Y2; e[2] += Z2;
            e[3] = fmaf(X2, X2, e[3]); e[4] = fmaf(Y2, Y2, e[4]); e[5] = fmaf(Z2, Z2, e[5]);
            e[6] = fmaf(X2, Y2, e[6]); e[7] = fmaf(X2, Z2, e[7]); e[8] = fmaf(Y2, Z2, e[8]);
            const int bt = 49 * hw + 48;
            s_p0[bt] = make_float4(e[0], e[1], e[2], e[3]);
            s_p1[bt] = make_float4(e[4], e[5], e[6], e[7]);
            s_p2[bt] = e[8];
        }
    }
    __syncthreads();                                   // B2: moments visible block-wide

    // ========== beta pass: 3 betas/lane, regs + segmented scan, store s_bp ======
    {
        const int blkL = (hw < NBB) ? hw : (NBB - 1);   // clamp for loads only
        const int o0 = 3 * sl;
        const int lo = (kb < 0) ? -kb : 0;
        const int hi = (K - kb < NBB * 48) ? (K - kb) : (NBB * 48);

        const float4 T0 = s_p0[49 * blkL + 48];
        const float4 T1 = s_p1[49 * blkL + 48];
        const float  Tz = s_p2[49 * blkL + 48];

        float4 vb[3];
        float v4[4] = {0.f, 0.f, 0.f, 0.f};
#pragma unroll
        for (int r = 0; r < 3; ++r) {
            const int o = o0 + r;
            const float4 A0 = s_p0[49 * blkL + o];
            const float4 A1 = s_p1[49 * blkL + o];
            const float  Az = s_p2[49 * blkL + o];
            const float4 B0 = s_p0[49 * (blkL + 1) + o];
            const float4 B1 = s_p1[49 * (blkL + 1) + o];
            const float  Bz = s_p2[49 * (blkL + 1) + o];

            float4 out = make_float4(0.f, 0.f, 0.f, 0.f);
            const int i = 48 * hw + o;
            if (i >= lo && i < hi) {
                const float Sx  = T0.x - A0.x + B0.x;
                const float Sy  = T0.y - A0.y + B0.y;
                const float Sz  = T0.z - A0.z + B0.z;
                const float Mxx = T0.w - A0.w + B0.w;
                const float Myy = T1.x - A1.x + B1.x;
                const float Mzz = T1.y - A1.y + B1.y;
                const float Mxy = T1.z - A1.z + B1.z;
                const float Mxz = T1.w - A1.w + B1.w;
                const float Myz = Tz   - Az   + Bz;

                const float Sxp = Sx + 48.f * XOFF;   // = 48*m_r
                const float Syp = Sy + 48.f * XOFF;
                const float Szp = Sz + 48.f * XOFF;
                const float Pyz = Syp * Szp, Pxz = Sxp * Szp, Pxy = Sxp * Syp;
                const float inv = rcp_fast(Pyz * Sxp);   // 1/(Sxp*Syp*Szp)
                const float c48inv = 48.f * inv;

                if (fastW) {
                    // W = [[0,1,-1],[-2,1,1]]: a0=(0,Pxz,-Pxy), a1=(-2Pyz,Pxz,Pxy)
                    const float t1 = Pxz * Sy, t2 = Pxy * Sz, t3 = Pyz * Sx;
                    const float T0s = t1 - t2;
                    const float T1s = fmaf(-2.f, t3, t1 + t2);
                    const float Pxz2 = Pxz * Pxz, Pxy2 = Pxy * Pxy;
                    const float csh = fmaf(Pxz2, Myy, Pxy2 * Mzz);
                    const float dsh = 2.f * (Pxz * Pxy) * Myz;
                    const float q0 = (csh - dsh) - T0s * T0s * (1.f / 48.f);
                    const float P4 = 4.f * Pyz;
                    float q1 = csh + dsh;
                    q1 = fmaf(P4 * Pyz, Mxx, q1);
                    q1 = fmaf(-(P4 * Pxz), Mxy, q1);
                    q1 = fmaf(-(P4 * Pxy), Mxz, q1);
                    q1 -= T1s * T1s * (1.f / 48.f);
                    const float alpha = q0 * rsqrt_fast(q0 * q1);   // sqrt(q0/q1)
                    out.x = (-2.f * alpha) * (Pyz * c48inv);
                    out.y = (1.f + alpha) * (Pxz * c48inv);
                    out.z = (alpha - 1.f) * (Pxy * c48inv);
                    out.w = 0.f;                                    // r0 = r1 = 0
                } else {
                    const float a0r = W00 * Pyz, a0g = W01 * Pxz, a0b = W02 * Pxy;
                    const float a1r = W10 * Pyz, a1g = W11 * Pxz, a1b = W12 * Pxy;
                    const float T0s = a0r * Sx + a0g * Sy + a0b * Sz;
                    const float T1s = a1r * Sx + a1g * Sy + a1b * Sz;
                    const float q0 = a0r * a0r * Mxx + a0g * a0g * Myy + a0b * a0b * Mzz
                                   + 2.f * (a0r * a0g * Mxy + a0r * a0b * Mxz + a0g * a0b * Myz)
                                   - T0s * T0s * (1.f / 48.f);
                    const float q1 = a1r * a1r * Mxx + a1g * a1g * Myy + a1b * a1b * Mzz
                                   + 2.f * (a1r * a1g * Mxy + a1r * a1b * Mxz + a1g * a1b * Myz)
                                   - T1s * T1s * (1.f / 48.f);
                    const float alpha = q0 * rsqrt_fast(q0 * q1);
                    out.x = fmaf(alpha, W10, W00) * (Pyz * c48inv);
                    out.y = fmaf(alpha, W11, W01) * (Pxz * c48inv);
                    out.z = fmaf(alpha, W12, W02) * (Pxy * c48inv);
                    out.w = fmaf(alpha, r1, r0);
                }
            }
            vb[r] = out;
            v4[0] += out.x; v4[1] += out.y; v4[2] += out.z; v4[3] += out.w;
        }

        float p4[4];
#pragma unroll
        for (int c = 0; c < 4; ++c) p4[c] = v4[c];
#pragma unroll
        for (int d = 1; d < 16; d <<= 1) {
#pragma unroll
            for (int c = 0; c < 4; ++c) {
                const float u = __shfl_up_sync(0xffffffffu, p4[c], d);
                if (sl >= d) p4[c] += u;
            }
        }
        // s_bp is a separate region: store immediately, no intervening barrier
        if (hw < NBB) {
            float e0 = p4[0] - v4[0], e1 = p4[1] - v4[1];
            float e2 = p4[2] - v4[2], e3 = p4[3] - v4[3];
            const int bp = 49 * hw + o0;
            s_bp[bp] = make_float4(e0, e1, e2, e3);
            e0 += vb[0].x; e1 += vb[0].y; e2 += vb[0].z; e3 += vb[0].w;
            s_bp[bp + 1] = make_float4(e0, e1, e2, e3);
            e0 += vb[1].x; e1 += vb[1].y; e2 += vb[1].z; e3 += vb[1].w;
            s_bp[bp + 2] = make_float4(e0, e1, e2, e3);
            if (sl == 15) {
                e0 += vb[2].x; e1 += vb[2].y; e2 += vb[2].z; e3 += vb[2].w;
                s_bp[49 * hw + 48] = make_float4(e0, e1, e2, e3);
            }
        }
    }
    __syncthreads();                                   // B4: beta prefixes visible

    // ================= output pass =================
#pragma unroll
    for (int c0 = 0; c0 < 3; ++c0) {
        const int m = t + c0 * BK;
        if (m < WPB) {
            const int a = m / 48;
            const int o = m - 48 * a;
            const float4 P48 = s_bp[49 * a + 48];
            const float4 Po  = s_bp[49 * a + o];
            const float4 Q   = s_bp[49 * (a + 1) + o];
            const int n = n0 + m;
            if (n < N) {
                const float* xp = s_buf + 3 + 3 * (m + HALO);
                const float xr = xp[0] + XOFF;
                const float xg = xp[1] + XOFF;
                const float xb = xp[2] + XOFF;
                const float Br = P48.x - Po.x + Q.x;
                const float Bg = P48.y - Po.y + Q.y;
                const float Bb = P48.z - Po.z + Q.z;
                const float G  = P48.w - Po.w + Q.w;
                H[n] = fmaf(xr, Br, fmaf(xg, Bg, fmaf(xb, Bb, -G)));
            }
        }
    }
}

extern "C" void kernel_launch(void* const* d_in, const int* in_sizes, int n_in,
                              void* d_out, int out_size) {
    const float* x  = (const float*)d_in[0];   // rgbs [1, N, 3]
    const float* Wm = (const float*)d_in[1];   // W [2,3]
    // d_in[2] = bias: cancels exactly (h is window-mean-centered).

    const int N = in_sizes[0] / 3;
    const int K = N - WIN;
    float* H = (float*)d_out;

    const int grid = (N + WPB - 1) / WPB;
    pos_kernel<<<grid, BK>>>(x, Wm, H, N, K);
}